// round 2
// baseline (speedup 1.0000x reference)
#include <cuda_runtime.h>
#include <cuda_bf16.h>

#define NPAIR 1024
#define NN 128
#define CC 64
#define NDIAG 255

#define INFV 1e30f
#define LOG2E 1.4426950408889634f
#define LN2f  0.6931471805599453f

__device__ __forceinline__ float ex2f(float x) {
    float r; asm("ex2.approx.ftz.f32 %0, %1;" : "=f"(r) : "f"(x)); return r;
}
__device__ __forceinline__ float lg2f(float x) {
    float r; asm("lg2.approx.ftz.f32 %0, %1;" : "=f"(r) : "f"(x)); return r;
}

// D stored diagonal-major, bf16, pre-scaled by log2(e):
// g_D[p*NDIAG*NN + d*NN + i] = (x2[i]+y2[j]-2*dot(x_i,y_j)) * LOG2E,  j = d - i
__device__ __nv_bfloat16 g_D[(size_t)NPAIR * NDIAG * NN];
__device__ float g_bl[NPAIR];

// ---------------- Phase A: cost matrices (GEMM) + diag-major restage ----------------
__global__ void __launch_bounds__(256) dtw_cost_kernel(const float* __restrict__ x,
                                                       const float* __restrict__ y) {
    // xs[32][132], ys[32][132] (k-major, padded); reused as ds[64][130] for staging
    __shared__ float sAB[2 * 32 * 132];
    __shared__ float sx2[128];
    __shared__ float sy2[128];
    float* xs = sAB;
    float* ys = sAB + 32 * 132;

    const int p   = blockIdx.x;
    const int tid = threadIdx.x;
    const float* __restrict__ xb = x + (size_t)p * NN * CC;
    const float* __restrict__ yb = y + (size_t)p * NN * CC;

    const int tm = tid >> 4;     // 0..15
    const int tn = tid & 15;     // 0..15
    const int i0 = tm * 8;
    const int j0 = tn * 8;

    float c[8][8];
#pragma unroll
    for (int m = 0; m < 8; m++)
#pragma unroll
        for (int n = 0; n < 8; n++) c[m][n] = 0.f;

    float accx = 0.f, accy = 0.f;

    // two k-chunks of 32 to keep static smem under 48KB
    for (int kc = 0; kc < 2; kc++) {
        __syncthreads();
        const int kbase = kc * 32;
        for (int t = tid; t < 128 * 32; t += 256) {
            int i  = t >> 5;
            int kk = t & 31;
            xs[kk * 132 + i] = xb[i * CC + kbase + kk];
            ys[kk * 132 + i] = yb[i * CC + kbase + kk];
        }
        __syncthreads();

        // per-row sum of squares (accumulated across chunks in regs)
        if (tid < 128) {
#pragma unroll 8
            for (int kk = 0; kk < 32; kk++) { float v = xs[kk * 132 + tid]; accx += v * v; }
        } else {
            int ii = tid - 128;
#pragma unroll 8
            for (int kk = 0; kk < 32; kk++) { float v = ys[kk * 132 + ii]; accy += v * v; }
        }

        // 8x8 register-tiled Gram accumulation
#pragma unroll 4
        for (int kk = 0; kk < 32; kk++) {
            float4 a0 = *(const float4*)&xs[kk * 132 + i0];
            float4 a1 = *(const float4*)&xs[kk * 132 + i0 + 4];
            float4 b0 = *(const float4*)&ys[kk * 132 + j0];
            float4 b1 = *(const float4*)&ys[kk * 132 + j0 + 4];
            float a[8] = {a0.x, a0.y, a0.z, a0.w, a1.x, a1.y, a1.z, a1.w};
            float b[8] = {b0.x, b0.y, b0.z, b0.w, b1.x, b1.y, b1.z, b1.w};
#pragma unroll
            for (int m = 0; m < 8; m++)
#pragma unroll
                for (int n = 0; n < 8; n++)
                    c[m][n] = fmaf(a[m], b[n], c[m][n]);
        }
    }

    __syncthreads();
    if (tid < 128) sx2[tid] = accx; else sy2[tid - 128] = accy;

    // restage D through smem (row halves) -> coalesced diag-major global writes
    float* ds = sAB;  // [64][130]
    __nv_bfloat16* __restrict__ outD = g_D + (size_t)p * NDIAG * NN;

    for (int h = 0; h < 2; h++) {
        __syncthreads();
        if ((i0 >> 6) == h) {
            int ib = i0 - h * 64;
#pragma unroll
            for (int m = 0; m < 8; m++) {
                float xx = sx2[i0 + m];
#pragma unroll
                for (int n = 0; n < 8; n += 2) {
                    float2 v;
                    v.x = (xx + sy2[j0 + n]     - 2.f * c[m][n])     * LOG2E;
                    v.y = (xx + sy2[j0 + n + 1] - 2.f * c[m][n + 1]) * LOG2E;
                    *(float2*)&ds[(ib + m) * 130 + j0 + n] = v;
                }
            }
        }
        __syncthreads();
        for (int t = tid; t < NDIAG * 64; t += 256) {
            int dg = t >> 6;          // diagonal 0..254
            int il = t & 63;
            int i  = h * 64 + il;
            int j  = dg - i;
            if ((unsigned)j < (unsigned)NN)
                outD[dg * NN + i] = __float2bfloat16(ds[il * 130 + j]);
        }
    }
}

// ---------------- Phase B: soft-DTW wavefront DP ----------------
__global__ void __launch_bounds__(128) dtw_dp_kernel() {
    __shared__ float bufs[3][NN + 1];   // slot 0 = left/up boundary pad (INF)
    const int p = blockIdx.x;
    const int i = threadIdx.x;
    const __nv_bfloat16* __restrict__ Dp = g_D + (size_t)p * NDIAG * NN;

    bufs[0][i + 1] = INFV;
    bufs[1][i + 1] = INFV;
    bufs[2][i + 1] = INFV;
    if (i == 0) { bufs[0][0] = INFV; bufs[1][0] = INFV; bufs[2][0] = INFV; }

    float rleft = INFV;                 // R[i, j-1] carried in-register
    if (i == 0) {
        float d00 = __bfloat162float(Dp[0]);   // R(0,0) = D(0,0)  (corner softmin = 0)
        bufs[0][1] = d00;
        rleft = d00;
    }
    __syncthreads();

    float* pr1 = bufs[0];   // diagonal d-1
    float* pr2 = bufs[2];   // diagonal d-2 (virtual "-1" = INF)
    float* pc  = bufs[1];   // write target

    // prefetch D two diagonals ahead
    float dc = __bfloat162float(Dp[1 * NN + i]);
    float dn = __bfloat162float(Dp[2 * NN + i]);

    for (int d = 1; d < NDIAG; d++) {
        float dn2 = 0.f;
        if (d + 2 < NDIAG) dn2 = __bfloat162float(Dp[(d + 2) * NN + i]);

        float up = pr1[i];          // R[i-1, j]
        float dg = pr2[i];          // R[i-1, j-1]
        float lf = rleft;           // R[i, j-1]
        float m  = fminf(lf, fminf(up, dg));
        float s  = ex2f(m - lf) + ex2f(m - up) + ex2f(m - dg);
        float r  = dc + m - lg2f(s);             // base-2 units throughout
        bool valid = (i <= d) && (i >= d - (NN - 1));
        r = valid ? r : INFV;
        pc[i + 1] = r;
        rleft = r;

        float* t = pr2; pr2 = pr1; pr1 = pc; pc = t;
        dc = dn; dn = dn2;
        __syncthreads();
    }

    if (i == NN - 1) g_bl[p] = rleft * LN2f;     // back to natural log units
}

// ---------------- Phase C: deterministic batch reduction ----------------
__global__ void dtw_reduce_kernel(float* __restrict__ out) {
    int b = threadIdx.x;
    if (b < 32) {
        float s = 0.f;
#pragma unroll
        for (int k = 0; k < 32; k++) s += g_bl[b * 32 + k];
        out[b] = s;
    }
}

extern "C" void kernel_launch(void* const* d_in, const int* in_sizes, int n_in,
                              void* d_out, int out_size) {
    (void)in_sizes; (void)n_in; (void)out_size;
    const float* x  = (const float*)d_in[0];
    const float* xr = (const float*)d_in[1];
    dtw_cost_kernel<<<NPAIR, 256>>>(x, xr);
    dtw_dp_kernel<<<NPAIR, 128>>>();
    dtw_reduce_kernel<<<1, 32>>>((float*)d_out);
}

// round 3
// speedup vs baseline: 1.1731x; 1.1731x over previous
#include <cuda_runtime.h>
#include <cuda_bf16.h>

#define NPAIR 1024
#define NN 128
#define CC 64
#define NDIAG 255
#define DSTRIDE 131   // halves; word-stride 65 (odd) -> conflict-free DP reads

#define INFV 1e30f
#define LOG2E 1.4426950408889634f
#define LN2f  0.6931471805599453f

__device__ float g_bl[NPAIR];

__device__ __forceinline__ float ex2f(float x) {
    float r; asm("ex2.approx.ftz.f32 %0, %1;" : "=f"(r) : "f"(x)); return r;
}
__device__ __forceinline__ float lg2f(float x) {
    float r; asm("lg2.approx.ftz.f32 %0, %1;" : "=f"(r) : "f"(x)); return r;
}

// ---------------- Fused: GEMM -> smem D (bf16) -> wavefront DP ----------------
__global__ void __launch_bounds__(256, 2) dtw_fused_kernel(const float* __restrict__ x,
                                                           const float* __restrict__ y) {
    // Phase 1 view: xs[32][132], ys[32][132] fp32 staging (33792 B)
    // Phase 2 view: Dsh[128][131] bf16 (33536 B) -- aliased after staging dies
    __shared__ char sraw[2 * 32 * 132 * 4];
    __shared__ float sx2[NN];
    __shared__ float sy2[NN];
    __shared__ float bufs[3][NN + 1];

    float* xs = (float*)sraw;
    float* ys = xs + 32 * 132;
    __nv_bfloat16* Dsh = (__nv_bfloat16*)sraw;

    const int p   = blockIdx.x;
    const int tid = threadIdx.x;
    const float* __restrict__ xb = x + (size_t)p * NN * CC;
    const float* __restrict__ yb = y + (size_t)p * NN * CC;

    const int tm = tid >> 4;     // 0..15
    const int tn = tid & 15;     // 0..15
    const int i0 = tm * 8;
    const int j0 = tn * 8;

    float c[8][8];
#pragma unroll
    for (int m = 0; m < 8; m++)
#pragma unroll
        for (int n = 0; n < 8; n++) c[m][n] = 0.f;

    float accx = 0.f, accy = 0.f;

    for (int kc = 0; kc < 2; kc++) {
        __syncthreads();
        const int kbase = kc * 32;
        for (int t = tid; t < 128 * 32; t += 256) {
            int i  = t >> 5;
            int kk = t & 31;
            xs[kk * 132 + i] = xb[i * CC + kbase + kk];
            ys[kk * 132 + i] = yb[i * CC + kbase + kk];
        }
        __syncthreads();

        if (tid < 128) {
#pragma unroll 8
            for (int kk = 0; kk < 32; kk++) { float v = xs[kk * 132 + tid]; accx += v * v; }
        } else {
            int ii = tid - 128;
#pragma unroll 8
            for (int kk = 0; kk < 32; kk++) { float v = ys[kk * 132 + ii]; accy += v * v; }
        }

#pragma unroll 4
        for (int kk = 0; kk < 32; kk++) {
            float4 a0 = *(const float4*)&xs[kk * 132 + i0];
            float4 a1 = *(const float4*)&xs[kk * 132 + i0 + 4];
            float4 b0 = *(const float4*)&ys[kk * 132 + j0];
            float4 b1 = *(const float4*)&ys[kk * 132 + j0 + 4];
            float a[8] = {a0.x, a0.y, a0.z, a0.w, a1.x, a1.y, a1.z, a1.w};
            float b[8] = {b0.x, b0.y, b0.z, b0.w, b1.x, b1.y, b1.z, b1.w};
#pragma unroll
            for (int m = 0; m < 8; m++)
#pragma unroll
                for (int n = 0; n < 8; n++)
                    c[m][n] = fmaf(a[m], b[n], c[m][n]);
        }
    }

    __syncthreads();
    if (tid < 128) sx2[tid] = accx; else sy2[tid - 128] = accy;
    __syncthreads();               // sx2/sy2 visible; staging buffers now dead

    // epilogue: D row-major bf16 into aliased smem, pre-scaled by log2(e)
#pragma unroll
    for (int m = 0; m < 8; m++) {
        float xx = sx2[i0 + m];
#pragma unroll
        for (int n = 0; n < 8; n++) {
            float v = (xx + sy2[j0 + n] - 2.f * c[m][n]) * LOG2E;
            Dsh[(i0 + m) * DSTRIDE + (j0 + n)] = __float2bfloat16(v);
        }
    }
    __syncthreads();

    if (tid >= 128) return;        // warps 4-7 done; DP uses named barrier below
    const int i = tid;

#define BARD() asm volatile("bar.sync 1, 128;" ::: "memory")

    bufs[0][i + 1] = INFV;
    bufs[1][i + 1] = INFV;
    bufs[2][i + 1] = INFV;
    if (i == 0) { bufs[0][0] = INFV; bufs[1][0] = INFV; bufs[2][0] = INFV; }

    float rleft = INFV;
    if (i == 0) {
        float d00 = __bfloat162float(Dsh[0]);   // R(0,0) = D(0,0)
        bufs[0][1] = d00;
        rleft = d00;
    }
    BARD();

    float* pr1 = bufs[0];   // diagonal d-1
    float* pr2 = bufs[2];   // diagonal d-2 (virtual "-1" = INF)
    float* pc  = bufs[1];

    // D value for d=1 (j = 1-i)
    float dc = 0.f;
    if ((unsigned)(1 - i) < (unsigned)NN)
        dc = __bfloat162float(Dsh[i * DSTRIDE + (1 - i)]);

    for (int d = 1; d < NDIAG; d++) {
        // prefetch D for d+1 (read-only smem -> fully overlapped)
        float dn = 0.f;
        int jn = d + 1 - i;
        if ((unsigned)jn < (unsigned)NN)
            dn = __bfloat162float(Dsh[i * DSTRIDE + jn]);

        float up = pr1[i];          // R[i-1, j]
        float dg = pr2[i];          // R[i-1, j-1]
        float lf = rleft;           // R[i, j-1]
        float m  = fminf(lf, fminf(up, dg));
        float s  = ex2f(m - lf) + ex2f(m - up) + ex2f(m - dg);
        float r  = dc + m - lg2f(s);             // base-2 units
        bool valid = (i <= d) && (i >= d - (NN - 1));
        r = valid ? r : INFV;
        pc[i + 1] = r;
        rleft = r;

        float* t = pr2; pr2 = pr1; pr1 = pc; pc = t;
        dc = dn;
        BARD();
    }

    if (i == NN - 1) g_bl[p] = rleft * LN2f;
#undef BARD
}

// ---------------- deterministic batch reduction ----------------
__global__ void dtw_reduce_kernel(float* __restrict__ out) {
    int b = threadIdx.x;
    if (b < 32) {
        float s = 0.f;
#pragma unroll
        for (int k = 0; k < 32; k++) s += g_bl[b * 32 + k];
        out[b] = s;
    }
}

extern "C" void kernel_launch(void* const* d_in, const int* in_sizes, int n_in,
                              void* d_out, int out_size) {
    (void)in_sizes; (void)n_in; (void)out_size;
    const float* x  = (const float*)d_in[0];
    const float* xr = (const float*)d_in[1];
    dtw_fused_kernel<<<NPAIR, 256>>>(x, xr);
    dtw_reduce_kernel<<<1, 32>>>((float*)d_out);
}